// round 1
// baseline (speedup 1.0000x reference)
#include <cuda_runtime.h>
#include <math.h>

#define N_ROWS 65536
#define DD 512
#define EE 256
#define TT 128
#define KK 5
#define KTOT 896   // D + E + T

#define BM 32
#define BK 16

// Scratch (allocation-free rule: __device__ globals)
__device__ float g_WqT[KTOT * DD];       // [896][512]
__device__ float g_query[(size_t)N_ROWS * DD];

__device__ __forceinline__ float clipf(float x, float lo, float hi) {
    return fminf(fmaxf(x, lo), hi);
}

// ---------------------------------------------------------------------------
// Kernel 0: transpose Wq [512,896] -> WqT [896,512]
// ---------------------------------------------------------------------------
__global__ void transpose_wq(const float* __restrict__ Wq) {
    int i = blockIdx.x * blockDim.x + threadIdx.x;   // over 896*512
    if (i < KTOT * DD) {
        int k = i / DD;
        int d = i - k * DD;
        g_WqT[i] = Wq[d * KTOT + k];
    }
}

// ---------------------------------------------------------------------------
// Kernel 1: query = tanh(LN(concat(clip(raw),clip(edge),clip(time)) @ Wq^T + bq))
// Block: 256 threads, computes BM=32 full rows x 512 cols.
// Thread (ty,tx): ty=tid>>6 owns rows ty*8..+7, tx=tid&63 owns cols {tx+64*j}.
// ---------------------------------------------------------------------------
__global__ __launch_bounds__(256) void qproj_kernel(
    const float* __restrict__ raw,
    const float* __restrict__ edge,
    const float* __restrict__ timeenc,
    const float* __restrict__ bq,
    const float* __restrict__ gamma,
    const float* __restrict__ beta)
{
    __shared__ float As[BK][BM];
    __shared__ float Bs[BK][DD];
    __shared__ float s_sum[BM];
    __shared__ float s_sq[BM];

    const int tid = threadIdx.x;
    const int tx = tid & 63;
    const int ty = tid >> 6;
    const int n0 = blockIdx.x * BM;
    const int lane = tid & 31;

    float acc[8][8];
    #pragma unroll
    for (int i = 0; i < 8; i++)
        #pragma unroll
        for (int j = 0; j < 8; j++) acc[i][j] = 0.f;

    for (int kt = 0; kt < KTOT; kt += BK) {
        // --- A tile (32 rows x 16 k), sanitize-clip on the fly ---
        #pragma unroll
        for (int e = tid; e < BM * BK; e += 256) {
            int m  = e >> 4;
            int kk = e & 15;
            int kg = kt + kk;
            int n  = n0 + m;
            float v;
            if (kg < DD)            v = raw[n * DD + kg];
            else if (kg < DD + EE)  v = edge[n * EE + (kg - DD)];
            else                    v = timeenc[n * TT + (kg - DD - EE)];
            As[kk][m] = clipf(v, -50.f, 50.f);
        }
        // --- B tile (16 k x 512 cols), coalesced float4 from WqT ---
        #pragma unroll
        for (int v4 = 0; v4 < 8; v4++) {
            int idx4 = tid + v4 * 256;
            int fidx = idx4 * 4;
            int kk = fidx >> 9;         // /512
            int c  = fidx & 511;
            float4 t = *reinterpret_cast<const float4*>(&g_WqT[(kt + kk) * DD + c]);
            *reinterpret_cast<float4*>(&Bs[kk][c]) = t;
        }
        __syncthreads();

        #pragma unroll
        for (int kk = 0; kk < BK; kk++) {
            float a[8], b[8];
            #pragma unroll
            for (int i = 0; i < 8; i++) a[i] = As[kk][ty * 8 + i];
            #pragma unroll
            for (int j = 0; j < 8; j++) b[j] = Bs[kk][tx + 64 * j];
            #pragma unroll
            for (int i = 0; i < 8; i++)
                #pragma unroll
                for (int j = 0; j < 8; j++)
                    acc[i][j] = fmaf(a[i], b[j], acc[i][j]);
        }
        __syncthreads();
    }

    // --- bias ---
    #pragma unroll
    for (int j = 0; j < 8; j++) {
        float bb = bq[tx + 64 * j];
        #pragma unroll
        for (int i = 0; i < 8; i++) acc[i][j] += bb;
    }

    // --- LayerNorm row reductions ---
    if (tid < BM) { s_sum[tid] = 0.f; s_sq[tid] = 0.f; }
    __syncthreads();

    float psum[8], psq[8];
    #pragma unroll
    for (int i = 0; i < 8; i++) {
        float s = 0.f, q = 0.f;
        #pragma unroll
        for (int j = 0; j < 8; j++) { s += acc[i][j]; q += acc[i][j] * acc[i][j]; }
        psum[i] = s; psq[i] = q;
    }
    #pragma unroll
    for (int off = 16; off > 0; off >>= 1) {
        #pragma unroll
        for (int i = 0; i < 8; i++) {
            psum[i] += __shfl_down_sync(0xffffffffu, psum[i], off);
            psq[i]  += __shfl_down_sync(0xffffffffu, psq[i],  off);
        }
    }
    if (lane == 0) {
        #pragma unroll
        for (int i = 0; i < 8; i++) {
            atomicAdd(&s_sum[ty * 8 + i], psum[i]);
            atomicAdd(&s_sq[ty * 8 + i],  psq[i]);
        }
    }
    __syncthreads();

    // --- normalize + tanh + store ---
    float gam[8], bet[8];
    #pragma unroll
    for (int j = 0; j < 8; j++) {
        int c = tx + 64 * j;
        gam[j] = gamma[c];
        bet[j] = beta[c];
    }
    #pragma unroll
    for (int i = 0; i < 8; i++) {
        int r = ty * 8 + i;
        float mu  = s_sum[r] * (1.f / DD);
        float var = s_sq[r] * (1.f / DD) - mu * mu;
        float rstd = rsqrtf(var + 1e-6f);
        #pragma unroll
        for (int j = 0; j < 8; j++) {
            int c = tx + 64 * j;
            float v = tanhf((acc[i][j] - mu) * rstd * gam[j] + bet[j]);
            g_query[(size_t)(n0 + r) * DD + c] = v;
        }
    }
}

// ---------------------------------------------------------------------------
// Kernel 2: per-row attention over K=5 prototypes + gate + residual + LN
// One 128-thread block per row. Thread owns cols d = tid + 128*j, j=0..3.
// ---------------------------------------------------------------------------
template <int M>
__device__ __forceinline__ void block_reduce(float* v, float (*red)[16], int tid) {
    int lane = tid & 31, w = tid >> 5;
    #pragma unroll
    for (int off = 16; off > 0; off >>= 1)
        #pragma unroll
        for (int m = 0; m < M; m++)
            v[m] += __shfl_down_sync(0xffffffffu, v[m], off);
    if (lane == 0)
        #pragma unroll
        for (int m = 0; m < M; m++) red[w][m] = v[m];
    __syncthreads();
    #pragma unroll
    for (int m = 0; m < M; m++)
        v[m] = red[0][m] + red[1][m] + red[2][m] + red[3][m];
    __syncthreads();
}

__global__ __launch_bounds__(128) void row_kernel(
    const float* __restrict__ raw,
    const float* __restrict__ timeenc,
    const float* __restrict__ proto,
    const float* __restrict__ Wg,
    const float* __restrict__ bg,
    const float* __restrict__ gamma,
    const float* __restrict__ beta,
    const float* __restrict__ temperature,
    float* __restrict__ out)
{
    const int n = blockIdx.x;
    const int tid = threadIdx.x;
    __shared__ float red[4][16];

    float q[4], r[4], p[KK][4];
    #pragma unroll
    for (int j = 0; j < 4; j++) {
        int d = tid + 128 * j;
        q[j] = g_query[(size_t)n * DD + d];
        r[j] = clipf(raw[n * DD + d], -50.f, 50.f);
    }
    float tv = timeenc[n * TT + tid];
    #pragma unroll
    for (int k = 0; k < KK; k++)
        #pragma unroll
        for (int j = 0; j < 4; j++)
            p[k][j] = proto[((size_t)n * KK + k) * DD + (tid + 128 * j)];

    // --- partials: [0]=||q_s||^2, [1..5]=||p_s||^2, [6..10]=q_s . p_s ---
    float part[11];
    {
        float qss = 0.f;
        #pragma unroll
        for (int j = 0; j < 4; j++) qss += q[j] * q[j];   // tanh out, clip20 no-op
        part[0] = qss;
        #pragma unroll
        for (int k = 0; k < KK; k++) {
            float pss = 0.f, pdot = 0.f;
            #pragma unroll
            for (int j = 0; j < 4; j++) {
                float ps = clipf(p[k][j], -20.f, 20.f);
                pss  += ps * ps;
                pdot += ps * q[j];
            }
            part[1 + k] = pss;
            part[6 + k] = pdot;
        }
    }
    block_reduce<11>(part, red, tid);

    // --- cosine sim, temperature, softmax (redundant per-thread) ---
    float qn = fmaxf(sqrtf(part[0]), 1e-6f);
    float temp = clipf(temperature[0], 0.5f, 5.0f) + 1e-4f;
    float sim[KK], mx = -1e30f;
    #pragma unroll
    for (int k = 0; k < KK; k++) {
        float s = part[6 + k] / (qn * fmaxf(sqrtf(part[1 + k]), 1e-6f));
        s = clipf(s, -15.f, 15.f) / temp;
        sim[k] = s;
        mx = fmaxf(mx, s);
    }
    float denom = 0.f, attn[KK];
    #pragma unroll
    for (int k = 0; k < KK; k++) { attn[k] = expf(sim[k] - mx); denom += attn[k]; }
    float inv = 1.f / denom;
    #pragma unroll
    for (int k = 0; k < KK; k++) attn[k] = clipf(attn[k] * inv, 0.f, 1.f);

    // --- candidate (unclipped prototypes), clip +-5 ---
    float cand[4];
    #pragma unroll
    for (int j = 0; j < 4; j++) {
        float c = 0.f;
        #pragma unroll
        for (int k = 0; k < KK; k++) c += attn[k] * p[k][j];
        cand[j] = clipf(c, -5.f, 5.f);
    }

    // --- gate: Wg . clip30([raw, cand, time_raw]) + bg ---
    float gp[1] = {0.f};
    #pragma unroll
    for (int j = 0; j < 4; j++) {
        int d = tid + 128 * j;
        gp[0] += Wg[d]      * clipf(r[j],    -30.f, 30.f);
        gp[0] += Wg[DD + d] * clipf(cand[j], -30.f, 30.f);
    }
    gp[0] += Wg[2 * DD + tid] * clipf(tv, -30.f, 30.f);
    block_reduce<1>(gp, red, tid);
    float gl = clipf(gp[0] + bg[0], -10.f, 10.f);
    float g = 1.f / (1.f + expf(-gl));

    // --- residual update + final LN + clip ---
    float u[4], st[2] = {0.f, 0.f};
    #pragma unroll
    for (int j = 0; j < 4; j++) {
        u[j] = 0.8f * r[j] + 0.2f * ((1.f - g) * r[j] + g * cand[j]);
        st[0] += u[j];
        st[1] += u[j] * u[j];
    }
    block_reduce<2>(st, red, tid);
    float mu  = st[0] * (1.f / DD);
    float var = st[1] * (1.f / DD) - mu * mu;
    float rstd = rsqrtf(var + 1e-6f);
    #pragma unroll
    for (int j = 0; j < 4; j++) {
        int d = tid + 128 * j;
        float o = (u[j] - mu) * rstd * gamma[d] + beta[d];
        out[(size_t)n * DD + d] = clipf(o, -10.f, 10.f);
    }
}

// ---------------------------------------------------------------------------
extern "C" void kernel_launch(void* const* d_in, const int* in_sizes, int n_in,
                              void* d_out, int out_size) {
    const float* raw   = (const float*)d_in[0];
    // d_in[1] = node_features (unused by the reference)
    const float* edge  = (const float*)d_in[2];
    const float* timee = (const float*)d_in[3];
    const float* proto = (const float*)d_in[4];
    const float* Wq    = (const float*)d_in[5];
    const float* bq    = (const float*)d_in[6];
    const float* Wg    = (const float*)d_in[7];
    const float* bg    = (const float*)d_in[8];
    const float* gamma = (const float*)d_in[9];
    const float* beta  = (const float*)d_in[10];
    const float* temp  = (const float*)d_in[11];
    float* out = (float*)d_out;

    transpose_wq<<<(KTOT * DD + 255) / 256, 256>>>(Wq);
    qproj_kernel<<<N_ROWS / BM, 256>>>(raw, edge, timee, bq, gamma, beta);
    row_kernel<<<N_ROWS, 128>>>(raw, timee, proto, Wg, bg, gamma, beta, temp, out);
}

// round 3
// speedup vs baseline: 3.5540x; 3.5540x over previous
#include <cuda_runtime.h>
#include <cuda_bf16.h>
#include <math.h>
#include <stdint.h>

#define N_ROWS 65536
#define DD 512
#define EE 256
#define TT 128
#define KK 5
#define KTOT 896

// GEMM tiling
#define BM 128
#define BN 128
#define BK 32
#define APAD 40            // padded k-stride (bf16 elems) to spread banks
#define NCH (KTOT / BK)    // 28 k-chunks

// ---------------- device scratch (no allocs allowed) ----------------
__device__ float g_xq[(size_t)N_ROWS * DD];                    // pre-LN query + bias
__device__ __align__(16) __nv_bfloat16 g_Wq_bf16[DD * KTOT];   // [512][896] K-major

__device__ __forceinline__ float clipf(float x, float lo, float hi) {
    return fminf(fmaxf(x, lo), hi);
}

// ---------------------------------------------------------------------------
// Kernel 0: Wq fp32 [512,896] -> bf16 (same K-major layout)
// ---------------------------------------------------------------------------
__global__ void convert_wq(const float* __restrict__ Wq) {
    int i = blockIdx.x * blockDim.x + threadIdx.x;
    if (i < DD * KTOT) g_Wq_bf16[i] = __float2bfloat16(Wq[i]);
}

// ---------------------------------------------------------------------------
// Kernel 1: x = concat(clip(raw),clip(edge),clip(time)) @ Wq^T + bq   (bf16 HMMA)
// CTA: 256 thr = 8 warps (2 x 4), warp tile 64x32, mma m16n8k16.
// Grid: (DD/BN = 4, N_ROWS/BM = 512).
// ---------------------------------------------------------------------------
__device__ __forceinline__ void mma16816(float c[4], uint32_t a0, uint32_t a1,
                                         uint32_t a2, uint32_t a3,
                                         uint32_t b0, uint32_t b1) {
    asm volatile(
        "mma.sync.aligned.m16n8k16.row.col.f32.bf16.bf16.f32 "
        "{%0,%1,%2,%3}, {%4,%5,%6,%7}, {%8,%9}, {%0,%1,%2,%3};\n"
        : "+f"(c[0]), "+f"(c[1]), "+f"(c[2]), "+f"(c[3])
        : "r"(a0), "r"(a1), "r"(a2), "r"(a3), "r"(b0), "r"(b1));
}

__global__ __launch_bounds__(256) void qproj_mma(
    const float* __restrict__ raw,
    const float* __restrict__ edge,
    const float* __restrict__ timeenc,
    const float* __restrict__ bq)
{
    __shared__ __align__(16) uint16_t As[2][BM * APAD];
    __shared__ __align__(16) uint16_t Bs[2][BN * APAD];

    const int tid  = threadIdx.x;
    const int lane = tid & 31;
    const int wid  = tid >> 5;
    const int wm   = wid >> 2;        // 0..1
    const int wn   = wid & 3;         // 0..3
    const int n0   = blockIdx.y * BM;
    const int nb0  = blockIdx.x * BN;

    float acc[4][4][4];
    #pragma unroll
    for (int mt = 0; mt < 4; mt++)
        #pragma unroll
        for (int nt = 0; nt < 4; nt++)
            #pragma unroll
            for (int j = 0; j < 4; j++) acc[mt][nt][j] = 0.f;

    float4 areg[4];
    uint4  breg[2];

    // ---- LDG chunk c into staging regs ----
    auto do_ldg = [&](int c) {
        const int kt = c * BK;
        const float* src; int stride;
        if (kt < DD)            { src = raw     + (size_t)n0 * DD + kt;             stride = DD; }
        else if (kt < DD + EE)  { src = edge    + (size_t)n0 * EE + (kt - DD);      stride = EE; }
        else                    { src = timeenc + (size_t)n0 * TT + (kt - DD - EE); stride = TT; }
        #pragma unroll
        for (int i = 0; i < 4; i++) {
            int id = tid + i * 256;           // 1024 float4s: A = 128 x 32 fp32
            int m  = id >> 3;
            int kk = (id & 7) * 4;
            areg[i] = *(const float4*)(src + (size_t)m * stride + kk);
        }
        const __nv_bfloat16* bsrc = g_Wq_bf16 + kt;
        #pragma unroll
        for (int i = 0; i < 2; i++) {
            int id = tid + i * 256;           // 512 uint4s: B = 128 x 32 bf16
            int r  = id >> 2;
            int kk = (id & 3) * 8;
            breg[i] = *(const uint4*)(bsrc + (size_t)(nb0 + r) * KTOT + kk);
        }
    };
    // ---- STS staging regs into buffer b (clip+convert for A) ----
    auto do_sts = [&](int b) {
        #pragma unroll
        for (int i = 0; i < 4; i++) {
            int id = tid + i * 256;
            int m  = id >> 3;
            int kk = (id & 7) * 4;
            float4 v = areg[i];
            v.x = clipf(v.x, -50.f, 50.f); v.y = clipf(v.y, -50.f, 50.f);
            v.z = clipf(v.z, -50.f, 50.f); v.w = clipf(v.w, -50.f, 50.f);
            __nv_bfloat162 lo = __float22bfloat162_rn(make_float2(v.x, v.y));
            __nv_bfloat162 hi = __float22bfloat162_rn(make_float2(v.z, v.w));
            uint2 pk;
            pk.x = *(uint32_t*)&lo; pk.y = *(uint32_t*)&hi;
            *(uint2*)&As[b][m * APAD + kk] = pk;
        }
        #pragma unroll
        for (int i = 0; i < 2; i++) {
            int id = tid + i * 256;
            int r  = id >> 2;
            int kk = (id & 3) * 8;
            *(uint4*)&Bs[b][r * APAD + kk] = breg[i];
        }
    };

    do_ldg(0);
    do_sts(0);
    __syncthreads();

    int buf = 0;
    for (int c = 0; c < NCH; c++) {
        if (c < NCH - 1) do_ldg(c + 1);

        // ---- compute chunk c from smem buffer `buf` ----
        #pragma unroll
        for (int ks = 0; ks < 2; ks++) {
            const int C = ks * 16 + (lane & 3) * 2;
            uint32_t af[4][4], bf[4][2];
            #pragma unroll
            for (int mt = 0; mt < 4; mt++) {
                int R = wm * 64 + mt * 16 + (lane >> 2);
                const uint16_t* ap = &As[buf][R * APAD + C];
                af[mt][0] = *(const uint32_t*)ap;
                af[mt][1] = *(const uint32_t*)(ap + 8 * APAD);
                af[mt][2] = *(const uint32_t*)(ap + 8);
                af[mt][3] = *(const uint32_t*)(ap + 8 * APAD + 8);
            }
            #pragma unroll
            for (int nt = 0; nt < 4; nt++) {
                int Nr = wn * 32 + nt * 8 + (lane >> 2);
                const uint16_t* bp = &Bs[buf][Nr * APAD + C];
                bf[nt][0] = *(const uint32_t*)bp;
                bf[nt][1] = *(const uint32_t*)(bp + 8);
            }
            #pragma unroll
            for (int mt = 0; mt < 4; mt++)
                #pragma unroll
                for (int nt = 0; nt < 4; nt++)
                    mma16816(acc[mt][nt], af[mt][0], af[mt][1], af[mt][2], af[mt][3],
                             bf[nt][0], bf[nt][1]);
        }

        if (c < NCH - 1) {
            do_sts(buf ^ 1);
            __syncthreads();
            buf ^= 1;
        }
    }

    // ---- epilogue: + bias, store fp32 pre-activation ----
    #pragma unroll
    for (int nt = 0; nt < 4; nt++) {
        int Cc = nb0 + wn * 32 + nt * 8 + (lane & 3) * 2;
        float b0 = bq[Cc], b1 = bq[Cc + 1];
        #pragma unroll
        for (int mt = 0; mt < 4; mt++) {
            int R = n0 + wm * 64 + mt * 16 + (lane >> 2);
            float2 o0 = make_float2(acc[mt][nt][0] + b0, acc[mt][nt][1] + b1);
            float2 o1 = make_float2(acc[mt][nt][2] + b0, acc[mt][nt][3] + b1);
            *(float2*)(g_xq + (size_t)R * DD + Cc)       = o0;
            *(float2*)(g_xq + (size_t)(R + 8) * DD + Cc) = o1;
        }
    }
}

// ---------------------------------------------------------------------------
// Kernel 2: LN+tanh on xq, then attention/gate/residual/final-LN per row.
// One 128-thread block per row; thread owns cols d = tid*4..tid*4+3.
// ---------------------------------------------------------------------------
template <int M>
__device__ __forceinline__ void block_reduce(float* v, float (*red)[16], int tid) {
    int lane = tid & 31, w = tid >> 5;
    #pragma unroll
    for (int off = 16; off > 0; off >>= 1)
        #pragma unroll
        for (int m = 0; m < M; m++)
            v[m] += __shfl_down_sync(0xffffffffu, v[m], off);
    if (lane == 0)
        #pragma unroll
        for (int m = 0; m < M; m++) red[w][m] = v[m];
    __syncthreads();
    #pragma unroll
    for (int m = 0; m < M; m++)
        v[m] = red[0][m] + red[1][m] + red[2][m] + red[3][m];
    __syncthreads();
}

__global__ __launch_bounds__(128) void row_kernel(
    const float* __restrict__ raw,
    const float* __restrict__ timeenc,
    const float* __restrict__ proto,
    const float* __restrict__ Wg,
    const float* __restrict__ bg,
    const float* __restrict__ gamma,
    const float* __restrict__ beta,
    const float* __restrict__ temperature,
    float* __restrict__ out)
{
    const int n = blockIdx.x;
    const int tid = threadIdx.x;
    const int d0 = tid * 4;
    __shared__ float red[4][16];

    float xq[4], r[4], p[KK][4], gm[4], bt[4];
    {
        float4 xv = *(const float4*)(g_xq + (size_t)n * DD + d0);
        xq[0] = xv.x; xq[1] = xv.y; xq[2] = xv.z; xq[3] = xv.w;
        float4 rv = *(const float4*)(raw + (size_t)n * DD + d0);
        r[0] = clipf(rv.x, -50.f, 50.f); r[1] = clipf(rv.y, -50.f, 50.f);
        r[2] = clipf(rv.z, -50.f, 50.f); r[3] = clipf(rv.w, -50.f, 50.f);
        float4 gv = *(const float4*)(gamma + d0);
        gm[0] = gv.x; gm[1] = gv.y; gm[2] = gv.z; gm[3] = gv.w;
        float4 bv = *(const float4*)(beta + d0);
        bt[0] = bv.x; bt[1] = bv.y; bt[2] = bv.z; bt[3] = bv.w;
    }
    float tv = timeenc[(size_t)n * TT + tid];
    #pragma unroll
    for (int k = 0; k < KK; k++) {
        float4 pv = *(const float4*)(proto + ((size_t)n * KK + k) * DD + d0);
        p[k][0] = pv.x; p[k][1] = pv.y; p[k][2] = pv.z; p[k][3] = pv.w;
    }

    // ---- query LN + tanh ----
    float st2[2] = {0.f, 0.f};
    #pragma unroll
    for (int j = 0; j < 4; j++) { st2[0] += xq[j]; st2[1] += xq[j] * xq[j]; }
    block_reduce<2>(st2, red, tid);
    {
        float mu   = st2[0] * (1.f / DD);
        float var  = st2[1] * (1.f / DD) - mu * mu;
        float rstd = rsqrtf(var + 1e-6f);
        #pragma unroll
        for (int j = 0; j < 4; j++)
            xq[j] = tanhf((xq[j] - mu) * rstd * gm[j] + bt[j]);   // xq is now q
    }

    // ---- partials: [0]=||q||^2, [1..5]=||p_s||^2, [6..10]=q.p_s ----
    float part[11];
    {
        float qss = 0.f;
        #pragma unroll
        for (int j = 0; j < 4; j++) qss += xq[j] * xq[j];
        part[0] = qss;
        #pragma unroll
        for (int k = 0; k < KK; k++) {
            float pss = 0.f, pdot = 0.f;
            #pragma unroll
            for (int j = 0; j < 4; j++) {
                float ps = clipf(p[k][j], -20.f, 20.f);
                pss  += ps * ps;
                pdot += ps * xq[j];
            }
            part[1 + k] = pss;
            part[6 + k] = pdot;
        }
    }
    block_reduce<11>(part, red, tid);

    float qn = fmaxf(sqrtf(part[0]), 1e-6f);
    float temp = clipf(temperature[0], 0.5f, 5.0f) + 1e-4f;
    float sim[KK], mx = -1e30f;
    #pragma unroll
    for (int k = 0; k < KK; k++) {
        float s = part[6 + k] / (qn * fmaxf(sqrtf(part[1 + k]), 1e-6f));
        s = clipf(s, -15.f, 15.f) / temp;
        sim[k] = s; mx = fmaxf(mx, s);
    }
    float denom = 0.f, attn[KK];
    #pragma unroll
    for (int k = 0; k < KK; k++) { attn[k] = expf(sim[k] - mx); denom += attn[k]; }
    float inv = 1.f / denom;
    #pragma unroll
    for (int k = 0; k < KK; k++) attn[k] = clipf(attn[k] * inv, 0.f, 1.f);

    float cand[4];
    #pragma unroll
    for (int j = 0; j < 4; j++) {
        float cc = 0.f;
        #pragma unroll
        for (int k = 0; k < KK; k++) cc += attn[k] * p[k][j];
        cand[j] = clipf(cc, -5.f, 5.f);
    }

    // ---- gate ----
    float gp[1] = {0.f};
    {
        float4 w0 = *(const float4*)(Wg + d0);
        float4 w1 = *(const float4*)(Wg + DD + d0);
        const float* wr0 = (const float*)&w0;
        const float* wr1 = (const float*)&w1;
        #pragma unroll
        for (int j = 0; j < 4; j++) {
            gp[0] += wr0[j] * clipf(r[j],    -30.f, 30.f);
            gp[0] += wr1[j] * clipf(cand[j], -30.f, 30.f);
        }
        gp[0] += Wg[2 * DD + tid] * clipf(tv, -30.f, 30.f);
    }
    block_reduce<1>(gp, red, tid);
    float gl = clipf(gp[0] + bg[0], -10.f, 10.f);
    float g = 1.f / (1.f + expf(-gl));

    // ---- residual + final LN ----
    float u[4], st[2] = {0.f, 0.f};
    #pragma unroll
    for (int j = 0; j < 4; j++) {
        u[j] = 0.8f * r[j] + 0.2f * ((1.f - g) * r[j] + g * cand[j]);
        st[0] += u[j];
        st[1] += u[j] * u[j];
    }
    block_reduce<2>(st, red, tid);
    float mu   = st[0] * (1.f / DD);
    float var  = st[1] * (1.f / DD) - mu * mu;
    float rstd = rsqrtf(var + 1e-6f);

    float4 o;
    float* op = (float*)&o;
    #pragma unroll
    for (int j = 0; j < 4; j++)
        op[j] = clipf((u[j] - mu) * rstd * gm[j] + bt[j], -10.f, 10.f);
    *(float4*)(out + (size_t)n * DD + d0) = o;
}

// ---------------------------------------------------------------------------
extern "C" void kernel_launch(void* const* d_in, const int* in_sizes, int n_in,
                              void* d_out, int out_size) {
    const float* raw   = (const float*)d_in[0];
    // d_in[1] = node_features (unused by reference)
    const float* edge  = (const float*)d_in[2];
    const float* timee = (const float*)d_in[3];
    const float* proto = (const float*)d_in[4];
    const float* Wq    = (const float*)d_in[5];
    const float* bq    = (const float*)d_in[6];
    const float* Wg    = (const float*)d_in[7];
    const float* bg    = (const float*)d_in[8];
    const float* gamma = (const float*)d_in[9];
    const float* beta  = (const float*)d_in[10];
    const float* temp  = (const float*)d_in[11];
    float* out = (float*)d_out;

    convert_wq<<<(DD * KTOT + 255) / 256, 256>>>(Wq);
    {
        dim3 grid(DD / BN, N_ROWS / BM);
        qproj_mma<<<grid, 256>>>(raw, edge, timee, bq);
    }
    row_kernel<<<N_ROWS, 128>>>(raw, timee, proto, Wg, bg, gamma, beta, temp, out);
}